// round 15
// baseline (speedup 1.0000x reference)
#include <cuda_runtime.h>

#define BN 4096
#define DD 2048
#define MARGINF 0.05f
#define HDELTA 0.1f
#define NPBLK 559           // live lower-triangle tiles (64-wide j-tiles)
#define NSIM  512           // k_sim blocks (8 rows each); all co-resident

// persistent scratch (no allocation allowed in kernel_launch)
__device__ float2 g_so[BN];        // {sim, overall} per SORTED position
__device__ int    g_hist[4096];    // bucket histogram (zeroed by scan block)
__device__ int    g_off[4096];     // exclusive bucket offsets (scatter cursor)
__device__ float  g_hub[BN];       // per-row huber partial (4 terms)
__device__ float  g_psum[NPBLK];   // per-block pair-loss partial
__device__ int    g_pcnt[NPBLK];   // per-block mask count partial
__device__ int    g_ticket;        // k_pairs final ticket (reset by its last block)
__device__ int    g_t2;            // k_sim hist ticket (reset by scan block)
__device__ volatile int g_ready;   // scan-done flag (reset by k_pairs last block)

__device__ __forceinline__ int bucketf(float o) {
    int b = (int)(o * 4096.0f);
    return b < 0 ? 0 : (b > 4095 ? 4095 : b);
}

// ---------------------------------------------------------------------------
// Kernel 1: fused {histogram -> (last block) scan} + warp-per-row cosine sim
// + huber + sorted scatter.  One-way g_ready flag (no grid barrier): the scan
// runs ~1.5us into the ~7-10us HBM phase, so the scatter's spin is near-zero.
// All 512 blocks are co-resident -> the flag-setter is always scheduled.
// Ordering: hist atomics consume their RETURN value (forces L2 completion
// before the ticket atomic); scan publishes g_off with per-thread fence ->
// __syncthreads -> flag store.  All counters return to 0 each run.
// ---------------------------------------------------------------------------
__global__ void __launch_bounds__(256) k_sim(
    const float* __restrict__ zr, const float* __restrict__ zp,
    const float* __restrict__ pred, const float* __restrict__ tgt) {
    __shared__ int ws[8];
    __shared__ int s_scan;
    __shared__ int s_dummy;
    int t    = threadIdx.x;
    int lane = t & 31;
    int warp = t >> 5;
    int blk  = blockIdx.x;
    int row  = blk * 8 + warp;

    // ---- histogram prologue: this block's 8 rows ----
    if (t == 0) s_dummy = 0;
    __syncthreads();
    if (t < 8) {
        int old = atomicAdd(&g_hist[bucketf(tgt[(blk * 8 + t) * 5 + 4])], 1);
        if (old > 100000) atomicAdd(&s_dummy, 1);   // consume return -> completion
    }
    __syncthreads();                                 // all 8 atomics completed
    if (t == 0) {
        int old = atomicAdd(&g_t2, 1);
        s_scan = (old == NSIM - 1);
    }
    __syncthreads();

    if (s_scan) {
        // ---- last-arriving block: exclusive scan g_hist[4096] -> g_off ----
        int base = t * 16;
        int h[16];
        int tot = 0;
#pragma unroll
        for (int k = 0; k < 16; k++) { h[k] = g_hist[base + k]; tot += h[k]; }
        int sc = tot;
#pragma unroll
        for (int o = 1; o < 32; o <<= 1) {
            int v = __shfl_up_sync(0xffffffffu, sc, o);
            if (lane >= o) sc += v;
        }
        if (lane == 31) ws[warp] = sc;
        __syncthreads();
        if (warp == 0) {
            int v = (lane < 8) ? ws[lane] : 0;
            int s2 = v;
#pragma unroll
            for (int o = 1; o < 8; o <<= 1) {
                int u = __shfl_up_sync(0xffffffffu, s2, o);
                if (lane >= o) s2 += u;
            }
            if (lane < 8) ws[lane] = s2 - v;   // exclusive warp bases
        }
        __syncthreads();
        int run = (sc - tot) + ws[warp];
#pragma unroll
        for (int k = 0; k < 16; k++) {
            g_off[base + k] = run;
            run += h[k];
            g_hist[base + k] = 0;              // restore for next replay
        }
        __threadfence();                       // publish this thread's g_off writes
        __syncthreads();                       // all threads' fences done
        if (t == 0) {
            g_t2 = 0;                          // restore for next replay
            g_ready = 1;                       // release
        }
    }

    // ---- cosine sim (HBM-bound; hides the scan) ----
    const float4* a = reinterpret_cast<const float4*>(zr) + (size_t)row * (DD / 4) + lane;
    const float4* b = reinterpret_cast<const float4*>(zp) + (size_t)row * (DD / 4) + lane;

    float d0 = 0.f, d1 = 0.f, na0 = 0.f, na1 = 0.f, nb0 = 0.f, nb1 = 0.f;
#pragma unroll
    for (int k = 0; k < 16; k += 2) {
        float4 x0 = a[k * 32];
        float4 y0 = b[k * 32];
        float4 x1 = a[(k + 1) * 32];
        float4 y1 = b[(k + 1) * 32];
        d0  += x0.x * y0.x + x0.y * y0.y + x0.z * y0.z + x0.w * y0.w;
        na0 += x0.x * x0.x + x0.y * x0.y + x0.z * x0.z + x0.w * x0.w;
        nb0 += y0.x * y0.x + y0.y * y0.y + y0.z * y0.z + y0.w * y0.w;
        d1  += x1.x * y1.x + x1.y * y1.y + x1.z * y1.z + x1.w * y1.w;
        na1 += x1.x * x1.x + x1.y * x1.y + x1.z * x1.z + x1.w * x1.w;
        nb1 += y1.x * y1.x + y1.y * y1.y + y1.z * y1.z + y1.w * y1.w;
    }
    float dot = d0 + d1, na = na0 + na1, nb = nb0 + nb1;
#pragma unroll
    for (int o = 16; o > 0; o >>= 1) {
        dot += __shfl_xor_sync(0xffffffffu, dot, o);
        na  += __shfl_xor_sync(0xffffffffu, na,  o);
        nb  += __shfl_xor_sync(0xffffffffu, nb,  o);
    }
    if (lane == 0) {
        float sim = dot / (fmaxf(sqrtf(na), 1e-8f) * fmaxf(sqrtf(nb), 1e-8f));
        float ov  = tgt[row * 5 + 4];
        float h = 0.f;
#pragma unroll
        for (int k = 0; k < 4; k++) {
            float d = pred[row * 4 + k] - tgt[row * 5 + k];
            float ad = fabsf(d);
            h += (ad <= HDELTA) ? (0.5f * d * d) : (HDELTA * (ad - 0.5f * HDELTA));
        }
        g_hub[row] = h;
        while (g_ready == 0) { }               // near-zero wait in practice
        int pos = atomicAdd(&g_off[bucketf(ov)], 1);   // atomic reads L2 truth
        g_so[pos] = make_float2(sim, ov);
    }
}

// ---------------------------------------------------------------------------
// Kernel 2: triangular masked margin reduction over sorted g_so + fused final.
// Tiles: i-chunk 256 (1 row/thread) x j-tile 64; live tiles per i-chunk ci:
// min(64, 4*ci+5); prefix T(ci) = 2*ci^2 + 3*ci, inverted in closed form.
// Dead tiles would need bucket multiplicity > 64 (probability ~0).
// Classification per thread:
//   b_i > b_jhi -> mask all-true (3 instr/pair, count = 64 free)
//   b_i < b_jlo -> all-false (skip)
//   else        -> exact o-compare (thin diagonal band; handles ties)
// relu identity: relu(s_j - s_i + m) = (s_j > t_i)*(s_j - t_i), t_i = s_i - m.
// Last block (ticket) reduces partials + huber -> out[0..2], resets
// g_ticket / g_ready for the next replay.
// ---------------------------------------------------------------------------
__global__ void __launch_bounds__(256) k_pairs(float* __restrict__ out) {
    __shared__ float sjx[64], sjy[64];
    __shared__ float wa[8], wh[8];
    __shared__ int   wc[8];
    __shared__ int   s_last;

    int t = threadIdx.x;
    // closed-form tile decode: T(ci) = 2ci^2 + 3ci, width min(64, 4ci+5)
    int bid = blockIdx.x;
    int ci, base;
    if (bid >= 495) { ci = 15; base = 495; }
    else {
        ci = (int)((sqrtf(8.f * (float)bid + 9.f) - 3.f) * 0.25f);
        base = 2 * ci * ci + 3 * ci;
        if (base > bid) { ci--; base = 2 * ci * ci + 3 * ci; }
        else if (2 * (ci + 1) * (ci + 1) + 3 * (ci + 1) <= bid) { ci++; base = 2 * ci * ci + 3 * ci; }
    }
    int jb = (bid - base) * 64, ib = ci * 256;

    float2 vi = g_so[ib + t];              // early load (latency overlap)
    if (t < 64) { float2 s = g_so[jb + t]; sjx[t] = s.x; sjy[t] = s.y; }
    __syncthreads();

    float ti = vi.x - MARGINF;
    float oi = vi.y;
    int b_i   = bucketf(oi);
    int b_jlo = bucketf(sjy[0]);
    int b_jhi = bucketf(sjy[63]);

    float a = 0.f;
    int   c = 0, kk = 0;
    if (b_i > b_jhi) {
        float a0 = 0.f, a1 = 0.f; int k0 = 0, k1 = 0;
#pragma unroll
        for (int j = 0; j < 64; j += 2) {
            float s0 = sjx[j], s1 = sjx[j + 1];
            if (s0 > ti) { a0 += s0; k0++; }
            if (s1 > ti) { a1 += s1; k1++; }
        }
        a = a0 + a1; kk = k0 + k1; c = 64;
    } else if (b_i >= b_jlo) {
        float a0 = 0.f, a1 = 0.f; int k0 = 0, k1 = 0, c0 = 0, c1 = 0;
#pragma unroll
        for (int j = 0; j < 64; j += 2) {
            float s0 = sjx[j], y0 = sjy[j];
            float s1 = sjx[j + 1], y1 = sjy[j + 1];
            bool m0 = oi > y0, m1 = oi > y1;
            if (m0) c0++;
            if (m0 && s0 > ti) { a0 += s0; k0++; }
            if (m1) c1++;
            if (m1 && s1 > ti) { a1 += s1; k1++; }
        }
        a = a0 + a1; kk = k0 + k1; c = c0 + c1;
    }
    a -= ti * (float)kk;

    c = __reduce_add_sync(0xffffffffu, c);
#pragma unroll
    for (int o = 16; o > 0; o >>= 1)
        a += __shfl_xor_sync(0xffffffffu, a, o);

    if ((t & 31) == 0) { wa[t >> 5] = a; wc[t >> 5] = c; }
    __syncthreads();
    if (t == 0) {
        a = 0.f; c = 0;
#pragma unroll
        for (int k = 0; k < 8; k++) { a += wa[k]; c += wc[k]; }
        g_psum[blockIdx.x] = a;
        g_pcnt[blockIdx.x] = c;
        __threadfence();
        int old = atomicAdd(&g_ticket, 1);
        s_last = (old == NPBLK - 1);
        if (s_last) { g_ticket = 0; g_ready = 0; }   // restore for next replay
    }
    __syncthreads();

    // ---- last block: final reduction (fixed-order -> deterministic) ----
    if (s_last) {
        float pa = 0.f;
        int   pc = 0;
        float h  = 0.f;
#pragma unroll
        for (int k = 0; k < 3; k++) {
            int idx = t + k * 256;
            if (idx < NPBLK) { pa += g_psum[idx]; pc += g_pcnt[idx]; }
        }
#pragma unroll
        for (int k = 0; k < 16; k++) h += g_hub[t + k * 256];
        pc = __reduce_add_sync(0xffffffffu, pc);
#pragma unroll
        for (int o = 16; o > 0; o >>= 1) {
            pa += __shfl_xor_sync(0xffffffffu, pa, o);
            h  += __shfl_xor_sync(0xffffffffu, h,  o);
        }
        if ((t & 31) == 0) { wa[t >> 5] = pa; wc[t >> 5] = pc; wh[t >> 5] = h; }
        __syncthreads();
        if (t == 0) {
            pa = 0.f; pc = 0; h = 0.f;
#pragma unroll
            for (int k = 0; k < 8; k++) { pa += wa[k]; pc += wc[k]; h += wh[k]; }
            float Lc = (pc > 0) ? (pa / fmaxf((float)pc, 1.f)) : 0.f;
            float Ls = h / (float)(BN * 4);
            out[0] = Lc + Ls;   // lambda_c = lambda_s = 1
            out[1] = Lc;
            out[2] = Ls;
        }
    }
}

extern "C" void kernel_launch(void* const* d_in, const int* in_sizes, int n_in,
                              void* d_out, int out_size) {
    const float* zr   = (const float*)d_in[0];
    const float* zp   = (const float*)d_in[1];
    const float* pred = (const float*)d_in[2];
    const float* tgt  = (const float*)d_in[3];

    k_sim<<<NSIM, 256>>>(zr, zp, pred, tgt);
    k_pairs<<<NPBLK, 256>>>((float*)d_out);
}

// round 16
// speedup vs baseline: 1.0077x; 1.0077x over previous
#include <cuda_runtime.h>

#define BN 4096
#define DD 2048
#define MARGINF 0.05f
#define HDELTA 0.1f
#define NPBLK 559           // live lower-triangle tiles (64-wide j-tiles)
#define NSIM  512           // k_sim blocks (8 rows each); all co-resident

// persistent scratch (no allocation allowed in kernel_launch)
__device__ float2 g_so[BN];        // {sim, overall} per SORTED position
__device__ int    g_hist[4096];    // bucket histogram (zeroed by scan block)
__device__ int    g_off[4096];     // exclusive bucket offsets (scatter cursor)
__device__ float  g_hub[BN];       // per-row huber partial (4 terms)
__device__ float  g_psum[NPBLK];   // per-block pair-loss partial
__device__ int    g_pcnt[NPBLK];   // per-block mask count partial
__device__ int    g_ticket;        // k_pairs final ticket (reset by its last block)
__device__ int    g_t2;            // k_sim hist ticket (reset by scan block)
__device__ volatile int g_ready;   // scan-done flag (reset by k_pairs last block)

__device__ __forceinline__ int bucketf(float o) {
    int b = (int)(o * 4096.0f);
    return b < 0 ? 0 : (b > 4095 ? 4095 : b);
}

// ---------------------------------------------------------------------------
// Kernel 1: fused {histogram -> (last block) scan} + warp-per-row cosine sim
// + huber + sorted scatter.  One-way g_ready flag (no grid barrier): the scan
// runs early in the HBM phase, so the scatter's spin is near-zero.  All 512
// blocks are co-resident -> the flag-setter is always scheduled.  Fences:
// hist-atomic -> threadfence -> ticket (release); scan block threadfence
// before reading hist (acquire); g_off published with fence+sync before flag.
// All counters return to 0 each run -> graph-replay safe.
// ---------------------------------------------------------------------------
__global__ void __launch_bounds__(256) k_sim(
    const float* __restrict__ zr, const float* __restrict__ zp,
    const float* __restrict__ pred, const float* __restrict__ tgt) {
    __shared__ int ws[8];
    __shared__ int s_scan;
    int t    = threadIdx.x;
    int lane = t & 31;
    int warp = t >> 5;
    int blk  = blockIdx.x;
    int row  = blk * 8 + warp;

    // ---- histogram prologue: this block's 8 rows ----
    if (t < 8) {
        atomicAdd(&g_hist[bucketf(tgt[(blk * 8 + t) * 5 + 4])], 1);
        __threadfence();                     // order hist atomic before ticket
    }
    __syncthreads();
    if (t == 0) {
        int old = atomicAdd(&g_t2, 1);
        s_scan = (old == NSIM - 1);
    }
    __syncthreads();

    if (s_scan) {
        // ---- last-arriving block: exclusive scan g_hist[4096] -> g_off ----
        __threadfence();                     // acquire all hist atomics
        int base = t * 16;
        int h[16];
        int tot = 0;
#pragma unroll
        for (int k = 0; k < 16; k++) { h[k] = g_hist[base + k]; tot += h[k]; }
        int sc = tot;
#pragma unroll
        for (int o = 1; o < 32; o <<= 1) {
            int v = __shfl_up_sync(0xffffffffu, sc, o);
            if (lane >= o) sc += v;
        }
        if (lane == 31) ws[warp] = sc;
        __syncthreads();
        if (warp == 0) {
            int v = (lane < 8) ? ws[lane] : 0;
            int s2 = v;
#pragma unroll
            for (int o = 1; o < 8; o <<= 1) {
                int u = __shfl_up_sync(0xffffffffu, s2, o);
                if (lane >= o) s2 += u;
            }
            if (lane < 8) ws[lane] = s2 - v; // exclusive warp bases
        }
        __syncthreads();
        int run = (sc - tot) + ws[warp];
#pragma unroll
        for (int k = 0; k < 16; k++) {
            g_off[base + k] = run;
            run += h[k];
            g_hist[base + k] = 0;            // restore for next replay
        }
        __threadfence();                     // publish this thread's g_off writes
        __syncthreads();                     // all threads' fences done
        if (t == 0) {
            g_t2 = 0;                        // restore for next replay
            g_ready = 1;                     // release
        }
    }

    // ---- cosine sim (HBM-bound; hides the scan) ----
    const float4* a = reinterpret_cast<const float4*>(zr) + (size_t)row * (DD / 4) + lane;
    const float4* b = reinterpret_cast<const float4*>(zp) + (size_t)row * (DD / 4) + lane;

    float d0 = 0.f, d1 = 0.f, na0 = 0.f, na1 = 0.f, nb0 = 0.f, nb1 = 0.f;
#pragma unroll
    for (int k = 0; k < 16; k += 2) {
        float4 x0 = a[k * 32];
        float4 y0 = b[k * 32];
        float4 x1 = a[(k + 1) * 32];
        float4 y1 = b[(k + 1) * 32];
        d0  += x0.x * y0.x + x0.y * y0.y + x0.z * y0.z + x0.w * y0.w;
        na0 += x0.x * x0.x + x0.y * x0.y + x0.z * x0.z + x0.w * x0.w;
        nb0 += y0.x * y0.x + y0.y * y0.y + y0.z * y0.z + y0.w * y0.w;
        d1  += x1.x * y1.x + x1.y * y1.y + x1.z * y1.z + x1.w * y1.w;
        na1 += x1.x * x1.x + x1.y * x1.y + x1.z * x1.z + x1.w * x1.w;
        nb1 += y1.x * y1.x + y1.y * y1.y + y1.z * y1.z + y1.w * y1.w;
    }
    float dot = d0 + d1, na = na0 + na1, nb = nb0 + nb1;
#pragma unroll
    for (int o = 16; o > 0; o >>= 1) {
        dot += __shfl_xor_sync(0xffffffffu, dot, o);
        na  += __shfl_xor_sync(0xffffffffu, na,  o);
        nb  += __shfl_xor_sync(0xffffffffu, nb,  o);
    }
    if (lane == 0) {
        float sim = dot / (fmaxf(sqrtf(na), 1e-8f) * fmaxf(sqrtf(nb), 1e-8f));
        float ov  = tgt[row * 5 + 4];
        float h = 0.f;
#pragma unroll
        for (int k = 0; k < 4; k++) {
            float d = pred[row * 4 + k] - tgt[row * 5 + k];
            float ad = fabsf(d);
            h += (ad <= HDELTA) ? (0.5f * d * d) : (HDELTA * (ad - 0.5f * HDELTA));
        }
        g_hub[row] = h;
        while (g_ready == 0) { }             // near-zero wait in practice
        int pos = atomicAdd(&g_off[bucketf(ov)], 1);   // atomic reads L2 truth
        g_so[pos] = make_float2(sim, ov);
    }
}

// ---------------------------------------------------------------------------
// Kernel 2: triangular masked margin reduction over sorted g_so + fused final.
// Tiles: i-chunk 256 (1 row/thread) x j-tile 64; live tiles per i-chunk ci:
// min(64, 4*ci+5); prefix T(ci) = 2*ci^2 + 3*ci, closed-form decode.
// BRANCH-FREE inner loops:
//   fast path (b_i > b_jhi, mask all-true):  a += relu(s_j - t_i)
//       -> FADD + FMNMX + FADD, 3 instr/pair, count = 64 constant.
//   band path: ternary selects (FSEL / ISETP), no BSSY/BSYNC divergence.
//   b_i < b_jlo: skip (all-false).
// Last block (ticket) reduces partials + huber -> out[0..2], resets
// g_ticket / g_ready for the next replay.
// ---------------------------------------------------------------------------
__global__ void __launch_bounds__(256) k_pairs(float* __restrict__ out) {
    __shared__ float sjx[64], sjy[64];
    __shared__ float wa[8], wh[8];
    __shared__ int   wc[8];
    __shared__ int   s_last;

    int t = threadIdx.x;
    // closed-form tile decode: T(ci) = 2ci^2 + 3ci, width min(64, 4ci+5)
    int bid = blockIdx.x;
    int ci, base;
    if (bid >= 495) { ci = 15; base = 495; }
    else {
        ci = (int)((sqrtf(8.f * (float)bid + 9.f) - 3.f) * 0.25f);
        base = 2 * ci * ci + 3 * ci;
        if (base > bid) { ci--; base = 2 * ci * ci + 3 * ci; }
        else if (2 * (ci + 1) * (ci + 1) + 3 * (ci + 1) <= bid) { ci++; base = 2 * ci * ci + 3 * ci; }
    }
    int jb = (bid - base) * 64, ib = ci * 256;

    float2 vi = g_so[ib + t];              // early load (latency overlap)
    if (t < 64) { float2 s = g_so[jb + t]; sjx[t] = s.x; sjy[t] = s.y; }
    __syncthreads();

    float ti = vi.x - MARGINF;
    float oi = vi.y;
    int b_i   = bucketf(oi);
    int b_jlo = bucketf(sjy[0]);
    int b_jhi = bucketf(sjy[63]);

    float a = 0.f;
    int   c = 0;
    if (b_i > b_jhi) {
        // mask all-true: pure relu accumulation, no predicates at all
        float a0 = 0.f, a1 = 0.f, a2 = 0.f, a3 = 0.f;
#pragma unroll
        for (int j = 0; j < 64; j += 4) {
            a0 += fmaxf(sjx[j]     - ti, 0.f);
            a1 += fmaxf(sjx[j + 1] - ti, 0.f);
            a2 += fmaxf(sjx[j + 2] - ti, 0.f);
            a3 += fmaxf(sjx[j + 3] - ti, 0.f);
        }
        a = (a0 + a1) + (a2 + a3);
        c = 64;
    } else if (b_i >= b_jlo) {
        // diagonal band: exact compares, branch-free selects
        float a0 = 0.f, a1 = 0.f;
        int   c0 = 0, c1 = 0;
#pragma unroll
        for (int j = 0; j < 64; j += 2) {
            bool m0 = oi > sjy[j];
            bool m1 = oi > sjy[j + 1];
            c0 += m0;
            c1 += m1;
            a0 += m0 ? fmaxf(sjx[j]     - ti, 0.f) : 0.f;
            a1 += m1 ? fmaxf(sjx[j + 1] - ti, 0.f) : 0.f;
        }
        a = a0 + a1;
        c = c0 + c1;
    }

    c = __reduce_add_sync(0xffffffffu, c);
#pragma unroll
    for (int o = 16; o > 0; o >>= 1)
        a += __shfl_xor_sync(0xffffffffu, a, o);

    if ((t & 31) == 0) { wa[t >> 5] = a; wc[t >> 5] = c; }
    __syncthreads();
    if (t == 0) {
        a = 0.f; c = 0;
#pragma unroll
        for (int k = 0; k < 8; k++) { a += wa[k]; c += wc[k]; }
        g_psum[blockIdx.x] = a;
        g_pcnt[blockIdx.x] = c;
        __threadfence();
        int old = atomicAdd(&g_ticket, 1);
        s_last = (old == NPBLK - 1);
        if (s_last) { g_ticket = 0; g_ready = 0; }   // restore for next replay
    }
    __syncthreads();

    // ---- last block: final reduction (fixed-order -> deterministic) ----
    if (s_last) {
        float pa = 0.f;
        int   pc = 0;
        float h  = 0.f;
#pragma unroll
        for (int k = 0; k < 3; k++) {
            int idx = t + k * 256;
            if (idx < NPBLK) { pa += g_psum[idx]; pc += g_pcnt[idx]; }
        }
#pragma unroll
        for (int k = 0; k < 16; k++) h += g_hub[t + k * 256];
        pc = __reduce_add_sync(0xffffffffu, pc);
#pragma unroll
        for (int o = 16; o > 0; o >>= 1) {
            pa += __shfl_xor_sync(0xffffffffu, pa, o);
            h  += __shfl_xor_sync(0xffffffffu, h,  o);
        }
        if ((t & 31) == 0) { wa[t >> 5] = pa; wc[t >> 5] = pc; wh[t >> 5] = h; }
        __syncthreads();
        if (t == 0) {
            pa = 0.f; pc = 0; h = 0.f;
#pragma unroll
            for (int k = 0; k < 8; k++) { pa += wa[k]; pc += wc[k]; h += wh[k]; }
            float Lc = (pc > 0) ? (pa / fmaxf((float)pc, 1.f)) : 0.f;
            float Ls = h / (float)(BN * 4);
            out[0] = Lc + Ls;   // lambda_c = lambda_s = 1
            out[1] = Lc;
            out[2] = Ls;
        }
    }
}

extern "C" void kernel_launch(void* const* d_in, const int* in_sizes, int n_in,
                              void* d_out, int out_size) {
    const float* zr   = (const float*)d_in[0];
    const float* zp   = (const float*)d_in[1];
    const float* pred = (const float*)d_in[2];
    const float* tgt  = (const float*)d_in[3];

    k_sim<<<NSIM, 256>>>(zr, zp, pred, tgt);
    k_pairs<<<NPBLK, 256>>>((float*)d_out);
}

// round 17
// speedup vs baseline: 1.0755x; 1.0673x over previous
#include <cuda_runtime.h>

#define BN 4096
#define DD 2048
#define MARGINF 0.05f
#define HDELTA 0.1f
#define NPBLK 559           // live lower-triangle tiles (64-wide j-tiles)
#define NSIM  512           // sim blocks (8 rows each); +1 scan block; co-resident

// persistent scratch (no allocation allowed in kernel_launch)
__device__ float2 g_so[BN];        // {sim, overall} per SORTED position
__device__ int    g_hist[4096];    // bucket histogram (zeroed by scan block)
__device__ int    g_off[4096];     // exclusive bucket offsets (scatter cursor)
__device__ float  g_hub[BN];       // per-row huber partial (4 terms)
__device__ float  g_psum[NPBLK];   // per-block pair-loss partial
__device__ int    g_pcnt[NPBLK];   // per-block mask count partial
__device__ int    g_ticket;        // k_pairs final ticket (reset by its last block)
__device__ int    g_t2;            // hist-done ticket (reset by scan block)
__device__ volatile int g_ready;   // scan-done flag (reset by k_pairs last block)

__device__ __forceinline__ int bucketf(float o) {
    int b = (int)(o * 4096.0f);
    return b < 0 ? 0 : (b > 4095 ? 4095 : b);
}

// ---------------------------------------------------------------------------
// Kernel 1: 513 blocks.  Blocks 0..511: {hist prologue for own 8 rows ->
// cosine sim -> huber -> wait g_ready (single poller) -> sorted scatter}.
// Block 512: SCAN-ONLY — spins until all 512 prologues ticked, scans
// g_hist[4096] -> g_off, zeroes g_hist, resets g_t2, sets g_ready, exits.
// The scan block never does sim work, so no block serializes scan+sim; its
// ~2us hides under the ~8-10us HBM phase.  All counters return to 0 each
// run -> graph-replay safe.  513 blocks co-resident (<=40 regs) -> the
// flag-setter is always scheduled -> no deadlock.
// ---------------------------------------------------------------------------
__global__ void __launch_bounds__(256) k_sim(
    const float* __restrict__ zr, const float* __restrict__ zp,
    const float* __restrict__ pred, const float* __restrict__ tgt) {
    __shared__ int ws[8];
    int t    = threadIdx.x;
    int lane = t & 31;
    int warp = t >> 5;
    int blk  = blockIdx.x;

    if (blk == NSIM) {
        // ---- dedicated scan block ----
        if (t == 0) {
            while (atomicAdd(&g_t2, 0) < NSIM) { }   // all hist prologues done
        }
        __syncthreads();
        __threadfence();                     // acquire all hist atomics
        int base = t * 16;
        int h[16];
        int tot = 0;
#pragma unroll
        for (int k = 0; k < 16; k++) { h[k] = g_hist[base + k]; tot += h[k]; }
        int sc = tot;
#pragma unroll
        for (int o = 1; o < 32; o <<= 1) {
            int v = __shfl_up_sync(0xffffffffu, sc, o);
            if (lane >= o) sc += v;
        }
        if (lane == 31) ws[warp] = sc;
        __syncthreads();
        if (warp == 0) {
            int v = (lane < 8) ? ws[lane] : 0;
            int s2 = v;
#pragma unroll
            for (int o = 1; o < 8; o <<= 1) {
                int u = __shfl_up_sync(0xffffffffu, s2, o);
                if (lane >= o) s2 += u;
            }
            if (lane < 8) ws[lane] = s2 - v; // exclusive warp bases
        }
        __syncthreads();
        int run = (sc - tot) + ws[warp];
#pragma unroll
        for (int k = 0; k < 16; k++) {
            g_off[base + k] = run;
            run += h[k];
            g_hist[base + k] = 0;            // restore for next replay
        }
        __threadfence();                     // publish g_off
        __syncthreads();
        if (t == 0) {
            g_t2 = 0;                        // restore for next replay
            g_ready = 1;                     // release
        }
        return;
    }

    int row = blk * 8 + warp;

    // ---- histogram prologue: this block's 8 rows ----
    if (t < 8) {
        atomicAdd(&g_hist[bucketf(tgt[(blk * 8 + t) * 5 + 4])], 1);
        __threadfence();                     // order hist atomic before ticket
    }
    __syncthreads();
    if (t == 0) atomicAdd(&g_t2, 1);

    // ---- cosine sim (HBM-bound; hides the scan) ----
    const float4* a = reinterpret_cast<const float4*>(zr) + (size_t)row * (DD / 4) + lane;
    const float4* b = reinterpret_cast<const float4*>(zp) + (size_t)row * (DD / 4) + lane;

    float d0 = 0.f, d1 = 0.f, na0 = 0.f, na1 = 0.f, nb0 = 0.f, nb1 = 0.f;
#pragma unroll
    for (int k = 0; k < 16; k += 2) {
        float4 x0 = a[k * 32];
        float4 y0 = b[k * 32];
        float4 x1 = a[(k + 1) * 32];
        float4 y1 = b[(k + 1) * 32];
        d0  += x0.x * y0.x + x0.y * y0.y + x0.z * y0.z + x0.w * y0.w;
        na0 += x0.x * x0.x + x0.y * x0.y + x0.z * x0.z + x0.w * x0.w;
        nb0 += y0.x * y0.x + y0.y * y0.y + y0.z * y0.z + y0.w * y0.w;
        d1  += x1.x * y1.x + x1.y * y1.y + x1.z * y1.z + x1.w * y1.w;
        na1 += x1.x * x1.x + x1.y * x1.y + x1.z * x1.z + x1.w * x1.w;
        nb1 += y1.x * y1.x + y1.y * y1.y + y1.z * y1.z + y1.w * y1.w;
    }
    float dot = d0 + d1, na = na0 + na1, nb = nb0 + nb1;
#pragma unroll
    for (int o = 16; o > 0; o >>= 1) {
        dot += __shfl_xor_sync(0xffffffffu, dot, o);
        na  += __shfl_xor_sync(0xffffffffu, na,  o);
        nb  += __shfl_xor_sync(0xffffffffu, nb,  o);
    }

    float sim = 0.f, ov = 0.f;
    if (lane == 0) {
        sim = dot / (fmaxf(sqrtf(na), 1e-8f) * fmaxf(sqrtf(nb), 1e-8f));
        ov  = tgt[row * 5 + 4];
        float h = 0.f;
#pragma unroll
        for (int k = 0; k < 4; k++) {
            float d = pred[row * 4 + k] - tgt[row * 5 + k];
            float ad = fabsf(d);
            h += (ad <= HDELTA) ? (0.5f * d * d) : (HDELTA * (ad - 0.5f * HDELTA));
        }
        g_hub[row] = h;
    }

    // single poller per block -> no 4096-way polling storm on g_ready
    __syncthreads();
    if (t == 0) {
        while (g_ready == 0) { }
    }
    __syncthreads();

    if (lane == 0) {
        int pos = atomicAdd(&g_off[bucketf(ov)], 1);   // atomic reads L2 truth
        g_so[pos] = make_float2(sim, ov);
    }
}

// ---------------------------------------------------------------------------
// Kernel 2: triangular masked margin reduction over sorted g_so + fused final.
// Tiles: i-chunk 256 (1 row/thread) x j-tile 64; live tiles per i-chunk ci:
// min(64, 4*ci+5); prefix T(ci) = 2*ci^2 + 3*ci, closed-form decode.
// Branch-free inner loops:
//   fast path (b_i > b_jhi, all-true): a += relu(s_j - t_i), count = 64.
//   band path: exact compares with selects; b_i < b_jlo: skip.
// relu identity: relu(s_j - s_i + m) = relu(s_j - t_i), t_i = s_i - m.
// Last block (ticket) reduces partials + huber -> out[0..2], resets
// g_ticket / g_ready for the next replay.
// ---------------------------------------------------------------------------
__global__ void __launch_bounds__(256) k_pairs(float* __restrict__ out) {
    __shared__ float sjx[64], sjy[64];
    __shared__ float wa[8], wh[8];
    __shared__ int   wc[8];
    __shared__ int   s_last;

    int t = threadIdx.x;
    // closed-form tile decode: T(ci) = 2ci^2 + 3ci, width min(64, 4ci+5)
    int bid = blockIdx.x;
    int ci, base;
    if (bid >= 495) { ci = 15; base = 495; }
    else {
        ci = (int)((sqrtf(8.f * (float)bid + 9.f) - 3.f) * 0.25f);
        base = 2 * ci * ci + 3 * ci;
        if (base > bid) { ci--; base = 2 * ci * ci + 3 * ci; }
        else if (2 * (ci + 1) * (ci + 1) + 3 * (ci + 1) <= bid) { ci++; base = 2 * ci * ci + 3 * ci; }
    }
    int jb = (bid - base) * 64, ib = ci * 256;

    float2 vi = g_so[ib + t];              // early load (latency overlap)
    if (t < 64) { float2 s = g_so[jb + t]; sjx[t] = s.x; sjy[t] = s.y; }
    __syncthreads();

    float ti = vi.x - MARGINF;
    float oi = vi.y;
    int b_i   = bucketf(oi);
    int b_jlo = bucketf(sjy[0]);
    int b_jhi = bucketf(sjy[63]);

    float a = 0.f;
    int   c = 0;
    if (b_i > b_jhi) {
        // mask all-true: pure relu accumulation, no predicates
        float a0 = 0.f, a1 = 0.f, a2 = 0.f, a3 = 0.f;
#pragma unroll
        for (int j = 0; j < 64; j += 4) {
            a0 += fmaxf(sjx[j]     - ti, 0.f);
            a1 += fmaxf(sjx[j + 1] - ti, 0.f);
            a2 += fmaxf(sjx[j + 2] - ti, 0.f);
            a3 += fmaxf(sjx[j + 3] - ti, 0.f);
        }
        a = (a0 + a1) + (a2 + a3);
        c = 64;
    } else if (b_i >= b_jlo) {
        // diagonal band: exact compares, branch-free selects
        float a0 = 0.f, a1 = 0.f;
        int   c0 = 0, c1 = 0;
#pragma unroll
        for (int j = 0; j < 64; j += 2) {
            bool m0 = oi > sjy[j];
            bool m1 = oi > sjy[j + 1];
            c0 += m0;
            c1 += m1;
            a0 += m0 ? fmaxf(sjx[j]     - ti, 0.f) : 0.f;
            a1 += m1 ? fmaxf(sjx[j + 1] - ti, 0.f) : 0.f;
        }
        a = a0 + a1;
        c = c0 + c1;
    }

    c = __reduce_add_sync(0xffffffffu, c);
#pragma unroll
    for (int o = 16; o > 0; o >>= 1)
        a += __shfl_xor_sync(0xffffffffu, a, o);

    if ((t & 31) == 0) { wa[t >> 5] = a; wc[t >> 5] = c; }
    __syncthreads();
    if (t == 0) {
        a = 0.f; c = 0;
#pragma unroll
        for (int k = 0; k < 8; k++) { a += wa[k]; c += wc[k]; }
        g_psum[blockIdx.x] = a;
        g_pcnt[blockIdx.x] = c;
        __threadfence();
        int old = atomicAdd(&g_ticket, 1);
        s_last = (old == NPBLK - 1);
        if (s_last) { g_ticket = 0; g_ready = 0; }   // restore for next replay
    }
    __syncthreads();

    // ---- last block: final reduction (fixed-order -> deterministic) ----
    if (s_last) {
        float pa = 0.f;
        int   pc = 0;
        float h  = 0.f;
#pragma unroll
        for (int k = 0; k < 3; k++) {
            int idx = t + k * 256;
            if (idx < NPBLK) { pa += g_psum[idx]; pc += g_pcnt[idx]; }
        }
#pragma unroll
        for (int k = 0; k < 16; k++) h += g_hub[t + k * 256];
        pc = __reduce_add_sync(0xffffffffu, pc);
#pragma unroll
        for (int o = 16; o > 0; o >>= 1) {
            pa += __shfl_xor_sync(0xffffffffu, pa, o);
            h  += __shfl_xor_sync(0xffffffffu, h,  o);
        }
        if ((t & 31) == 0) { wa[t >> 5] = pa; wc[t >> 5] = pc; wh[t >> 5] = h; }
        __syncthreads();
        if (t == 0) {
            pa = 0.f; pc = 0; h = 0.f;
#pragma unroll
            for (int k = 0; k < 8; k++) { pa += wa[k]; pc += wc[k]; h += wh[k]; }
            float Lc = (pc > 0) ? (pa / fmaxf((float)pc, 1.f)) : 0.f;
            float Ls = h / (float)(BN * 4);
            out[0] = Lc + Ls;   // lambda_c = lambda_s = 1
            out[1] = Lc;
            out[2] = Ls;
        }
    }
}

extern "C" void kernel_launch(void* const* d_in, const int* in_sizes, int n_in,
                              void* d_out, int out_size) {
    const float* zr   = (const float*)d_in[0];
    const float* zp   = (const float*)d_in[1];
    const float* pred = (const float*)d_in[2];
    const float* tgt  = (const float*)d_in[3];

    k_sim<<<NSIM + 1, 256>>>(zr, zp, pred, tgt);
    k_pairs<<<NPBLK, 256>>>((float*)d_out);
}